// round 2
// baseline (speedup 1.0000x reference)
#include <cuda_runtime.h>

// LieTransport: bilinear backward warp, L1-wavefront-optimized stores.
// h_prev: [B=4, C=64, H=128, W=128, R=16] fp32  (R innermost, 64B per (c,y,x))
// flow:   [B, 2, H, W] fp32
// dt:     [B] fp32
//
// One 512-thread block per x-pixel-PAIR (2x, 2x+1).
// Lane map: c = tid>>3 (64 channels), px = (tid>>2)&1, q = tid&3.
// => each warp's store covers 4 channels x 128B fully-aligned lines
//    (pixel pair is contiguous in the [.,.,y,x,R] layout).

#define Hd 128
#define Wd 128
#define Cd 64

__global__ __launch_bounds__(512, 4) void lie_transport_kernel(
    const float4* __restrict__ h4,
    const float*  __restrict__ flow,
    const float*  __restrict__ dt,
    float4*       __restrict__ out4)
{
    const int tid = threadIdx.x;
    const int c   = tid >> 3;          // 0..63
    const int px  = (tid >> 2) & 1;    // which pixel of the pair
    const int q   = tid & 3;           // float4 quarter of R=16

    const int pp = blockIdx.x;         // pair index
    const int x  = (((pp & (Wd/2 - 1)) << 1) | px);
    const int y  = (pp >> 6) & (Hd - 1);
    const int b  = pp >> 13;

    // --- sampling coordinates (uniform per (b,y,x)) ---
    const float d  = dt[b];
    const int   fb = ((b * 2) * Hd + y) * Wd + x;
    const float fx = flow[fb];
    const float fy = flow[fb + Hd * Wd];

    // base grid: linspace(-1,1,N)[i] = -1 + 2*i/(N-1)
    const float gx = fmaf((float)x, 2.0f / (Wd - 1), -1.0f) - fx * d;
    const float gy = fmaf((float)y, 2.0f / (Hd - 1), -1.0f) - fy * d;

    const float ix = fminf(fmaxf(((gx + 1.0f) * (float)Wd - 1.0f) * 0.5f, 0.0f), (float)(Wd - 1));
    const float iy = fminf(fmaxf(((gy + 1.0f) * (float)Hd - 1.0f) * 0.5f, 0.0f), (float)(Hd - 1));

    const float x0f = floorf(ix);
    const float y0f = floorf(iy);
    const float wx  = ix - x0f;
    const float wy  = iy - y0f;

    const int x0 = (int)x0f;
    const int y0 = (int)y0f;
    const int x1 = min(x0 + 1, Wd - 1);
    const int y1 = min(y0 + 1, Hd - 1);

    // float4 linear index: (((b*C + c)*H + yy)*W + xx)*4 + q
    const int cbase = (b * Cd + c) * (Hd * Wd * 4);

    const int i00 = cbase + (y0 * Wd + x0) * 4 + q;
    const int i01 = cbase + (y0 * Wd + x1) * 4 + q;
    const int i10 = cbase + (y1 * Wd + x0) * 4 + q;
    const int i11 = cbase + (y1 * Wd + x1) * 4 + q;

    // 4 independent LDG.128 -> MLP = 4
    const float4 v00 = h4[i00];
    const float4 v01 = h4[i01];
    const float4 v10 = h4[i10];
    const float4 v11 = h4[i11];

    float4 top, bot, r;
    top.x = fmaf(wx, v01.x - v00.x, v00.x);
    top.y = fmaf(wx, v01.y - v00.y, v00.y);
    top.z = fmaf(wx, v01.z - v00.z, v00.z);
    top.w = fmaf(wx, v01.w - v00.w, v00.w);

    bot.x = fmaf(wx, v11.x - v10.x, v10.x);
    bot.y = fmaf(wx, v11.y - v10.y, v10.y);
    bot.z = fmaf(wx, v11.z - v10.z, v10.z);
    bot.w = fmaf(wx, v11.w - v10.w, v10.w);

    r.x = fmaf(wy, bot.x - top.x, top.x);
    r.y = fmaf(wy, bot.y - top.y, top.y);
    r.z = fmaf(wy, bot.z - top.z, top.z);
    r.w = fmaf(wy, bot.w - top.w, top.w);

    // Fully coalesced: warp covers 4 channels x one full 128B line each.
    out4[cbase + (y * Wd + x) * 4 + q] = r;
}

extern "C" void kernel_launch(void* const* d_in, const int* in_sizes, int n_in,
                              void* d_out, int out_size)
{
    const float* h_prev = (const float*)d_in[0];
    const float* flow   = (const float*)d_in[1];
    const float* dt     = (const float*)d_in[2];
    float* out          = (float*)d_out;

    const int B = 4;
    dim3 grid(B * Hd * (Wd / 2));   // 32768 blocks, one per pixel pair
    dim3 block(512);

    lie_transport_kernel<<<grid, block>>>(
        (const float4*)h_prev, flow, dt, (float4*)out);
}

// round 3
// speedup vs baseline: 1.1279x; 1.1279x over previous
#include <cuda_runtime.h>

// LieTransport: bilinear backward warp.
// h_prev: [B=4, C=64, H=128, W=128, R=16] fp32  (R innermost, 64B per (c,y,x))
// flow:   [B, 2, H, W] fp32
// dt:     [B] fp32
//
// One 256-thread block per x-pixel-PAIR (2x, 2x+1); each thread handles the
// same (pixel, quarter) for TWO channels (c, c+32) -> 8 independent LDG.128
// in flight (MLP=8). Warp store instruction covers 4 channels x one full,
// aligned 128B line (pixel pair contiguous in memory). Stores are streaming
// (.cs) since output is never re-read.

#define Hd 128
#define Wd 128
#define Cd 64

__device__ __forceinline__ void stcs4(float4* p, float4 v) {
    __stcs(p, v);
}

__global__ __launch_bounds__(256, 4) void lie_transport_kernel(
    const float4* __restrict__ h4,
    const float*  __restrict__ flow,
    const float*  __restrict__ dt,
    float4*       __restrict__ out4)
{
    const int tid = threadIdx.x;
    const int q   = tid & 3;           // float4 quarter of R=16
    const int px  = (tid >> 2) & 1;    // which pixel of the pair
    const int cg  = tid >> 3;          // 0..31 -> channels cg and cg+32

    const int pp = blockIdx.x;         // pair index
    const int x  = (((pp & (Wd/2 - 1)) << 1) | px);
    const int y  = (pp >> 6) & (Hd - 1);
    const int b  = pp >> 13;

    // --- sampling coordinates (uniform per (b,y,x)) ---
    const float d  = dt[b];
    const int   fb = ((b * 2) * Hd + y) * Wd + x;
    const float fx = flow[fb];
    const float fy = flow[fb + Hd * Wd];

    const float gx = fmaf((float)x, 2.0f / (Wd - 1), -1.0f) - fx * d;
    const float gy = fmaf((float)y, 2.0f / (Hd - 1), -1.0f) - fy * d;

    const float ix = fminf(fmaxf(((gx + 1.0f) * (float)Wd - 1.0f) * 0.5f, 0.0f), (float)(Wd - 1));
    const float iy = fminf(fmaxf(((gy + 1.0f) * (float)Hd - 1.0f) * 0.5f, 0.0f), (float)(Hd - 1));

    const float x0f = floorf(ix);
    const float y0f = floorf(iy);
    const float wx  = ix - x0f;
    const float wy  = iy - y0f;

    const int x0 = (int)x0f;
    const int y0 = (int)y0f;
    const int x1 = min(x0 + 1, Wd - 1);
    const int y1 = min(y0 + 1, Hd - 1);

    // tap offsets within a channel plane (in float4 units), plus quarter
    const int t00 = (y0 * Wd + x0) * 4 + q;
    const int t01 = (y0 * Wd + x1) * 4 + q;
    const int t10 = (y1 * Wd + x0) * 4 + q;
    const int t11 = (y1 * Wd + x1) * 4 + q;
    const int tout = (y * Wd + x) * 4 + q;

    // channel plane bases (float4 units): plane = H*W*4 float4s
    const int baseA = (b * Cd + cg)        * (Hd * Wd * 4);
    const int baseB = (b * Cd + cg + 32)   * (Hd * Wd * 4);

    // --- issue all 8 loads before consuming any (MLP = 8) ---
    const float4 a00 = h4[baseA + t00];
    const float4 a01 = h4[baseA + t01];
    const float4 a10 = h4[baseA + t10];
    const float4 a11 = h4[baseA + t11];
    const float4 b00 = h4[baseB + t00];
    const float4 b01 = h4[baseB + t01];
    const float4 b10 = h4[baseB + t10];
    const float4 b11 = h4[baseB + t11];

    float4 top, bot, r;

    // channel A
    top.x = fmaf(wx, a01.x - a00.x, a00.x);
    top.y = fmaf(wx, a01.y - a00.y, a00.y);
    top.z = fmaf(wx, a01.z - a00.z, a00.z);
    top.w = fmaf(wx, a01.w - a00.w, a00.w);
    bot.x = fmaf(wx, a11.x - a10.x, a10.x);
    bot.y = fmaf(wx, a11.y - a10.y, a10.y);
    bot.z = fmaf(wx, a11.z - a10.z, a10.z);
    bot.w = fmaf(wx, a11.w - a10.w, a10.w);
    r.x = fmaf(wy, bot.x - top.x, top.x);
    r.y = fmaf(wy, bot.y - top.y, top.y);
    r.z = fmaf(wy, bot.z - top.z, top.z);
    r.w = fmaf(wy, bot.w - top.w, top.w);
    stcs4(&out4[baseA + tout], r);

    // channel B
    top.x = fmaf(wx, b01.x - b00.x, b00.x);
    top.y = fmaf(wx, b01.y - b00.y, b00.y);
    top.z = fmaf(wx, b01.z - b00.z, b00.z);
    top.w = fmaf(wx, b01.w - b00.w, b00.w);
    bot.x = fmaf(wx, b11.x - b10.x, b10.x);
    bot.y = fmaf(wx, b11.y - b10.y, b10.y);
    bot.z = fmaf(wx, b11.z - b10.z, b10.z);
    bot.w = fmaf(wx, b11.w - b10.w, b10.w);
    r.x = fmaf(wy, bot.x - top.x, top.x);
    r.y = fmaf(wy, bot.y - top.y, top.y);
    r.z = fmaf(wy, bot.z - top.z, top.z);
    r.w = fmaf(wy, bot.w - top.w, top.w);
    stcs4(&out4[baseB + tout], r);
}

extern "C" void kernel_launch(void* const* d_in, const int* in_sizes, int n_in,
                              void* d_out, int out_size)
{
    const float* h_prev = (const float*)d_in[0];
    const float* flow   = (const float*)d_in[1];
    const float* dt     = (const float*)d_in[2];
    float* out          = (float*)d_out;

    const int B = 4;
    dim3 grid(B * Hd * (Wd / 2));   // 32768 blocks, one per pixel pair
    dim3 block(256);

    lie_transport_kernel<<<grid, block>>>(
        (const float4*)h_prev, flow, dt, (float4*)out);
}